// round 10
// baseline (speedup 1.0000x reference)
#include <cuda_runtime.h>
#include <math.h>

#define BVOL  (128*128*128)
#define VOL   (2*BVOL)          // 4,194,304
#define PLANE (128*128)
#define PL2   (PLANE/2)         // float2 plane stride
#define FVOL  (2*3*BVOL)        // 12,582,912

#define NLCC 800                // 5x5 xy-tiles * 8 z-segs * 2 pairs * 2 batches
#define NREG 292
#define NTV  120
#define NTOT (NLCC + NREG + 2*NTV)   // 1332 = 3 waves at 3 CTAs/SM

__device__ double g_acc[12];    // zero-init; finalizer re-zeros each launch
__device__ unsigned int g_done;
// 0 reg | 1 gg0 2 pp0 3 gp0 | 4 gg1 5 pp1 6 gp1 | 7 tvgp0 8 tvsum0 | 9 tvgp1 10 tvsum1

__device__ __forceinline__ float warpSum(float v) {
#pragma unroll
    for (int o = 16; o; o >>= 1) v += __shfl_down_sync(0xffffffffu, v, o);
    return v;
}

__device__ __forceinline__ double accRead(int i) {
    return atomicAdd(&g_acc[i], 0.0);
}

__global__ void __launch_bounds__(512, 3)
fused_main(const float* __restrict__ F0,  const float* __restrict__ F0g,
           const float* __restrict__ I0,  const float* __restrict__ I0R,
           const float* __restrict__ I1,  const float* __restrict__ I1R,
           const float* __restrict__ S0,  const float* __restrict__ S0g,
           const float* __restrict__ S1,  const float* __restrict__ S1g,
           float* __restrict__ out) {
    __shared__ float4 smZ[2][32][16];   // (G0,G1,P0,P1) z-sum planes, double-buffered
    __shared__ float red[5][16];

    const int tx  = threadIdx.x;          // 0..15, owns x-elements 2tx,2tx+1
    const int ty  = threadIdx.y;          // 0..31
    const int lin = ty * 16 + tx;
    const int lane = lin & 31, wid = lin >> 5;
    const int bid = blockIdx.x;

    if (bid < NLCC) {
        // -------- fully fused LCC, float2 x-packing, width-16 shuffles ------
        int t = bid;
        int pb   = t & 3;  t >>= 2;      // pair*2 + batch
        int zseg = t & 7;  t >>= 3;      // 8 z-segments of 16
        int tyid = t % 5;                // 5 y-tiles of 28
        int txid = t / 5;                // 5 x-tiles of 28
        int pair = pb >> 1, n = pb & 1;
        const float* __restrict__ gt = pair ? I1  : I0;
        const float* __restrict__ pr = pair ? I1R : I0R;
        const int accBase = 1 + 3 * pair;

        const int x0 = txid * 28, y0 = tyid * 28, z0 = zseg * 16;
        const int ex = x0 + 2 * tx - 2;       // first x-element of this thread
        const int gy = y0 + ty - 2;
        const bool colValid = (gy >= 0) && (gy < 128) && (ex >= 0) && (ex < 128);
        const bool interYX = (tx >= 1) && (tx < 15) && (ty >= 2) && (ty < 30) && (gy < 128);
        const bool v0 = interYX && (ex < 128);
        const bool v1 = interYX && (ex + 1 < 128);

        const float2* __restrict__ pG = (const float2*)(gt + (n * BVOL + gy * 128 + ex)) ;
        const float2* __restrict__ pP = (const float2*)(pr + (n * BVOL + gy * 128 + ex));
        // NOTE: pointers only dereferenced when colValid (ex even -> aligned)

        const float2 zero2 = make_float2(0.f, 0.f);
        float2 a0 = zero2, a1 = zero2, a2 = zero2, a3 = zero2;
        float2 b0 = zero2, b1 = zero2, b2 = zero2, b3 = zero2;
        if (colValid) {
            if (z0 >= 2) { a0 = pG[(z0-2) * PL2]; b0 = pP[(z0-2) * PL2]; }
            if (z0 >= 1) { a1 = pG[(z0-1) * PL2]; b1 = pP[(z0-1) * PL2]; }
            a2 = pG[z0 * PL2];       b2 = pP[z0 * PL2];
            a3 = pG[(z0+1) * PL2];   b3 = pP[(z0+1) * PL2];
        }

        float agg = 0.f, app = 0.f, agp = 0.f;

#pragma unroll 4
        for (int zi = 0; zi < 16; zi++) {
            const int buf = zi & 1;
            const int zl  = z0 + zi + 2;
            float2 na = zero2, nb = zero2;
            if (colValid && zl < 128) {
                na = pG[zl * PL2];
                nb = pP[zl * PL2];
            }
            // z-sums (componentwise), packed store
            float zG0 = ((a0.x + a1.x) + (a2.x + a3.x)) + na.x;
            float zG1 = ((a0.y + a1.y) + (a2.y + a3.y)) + na.y;
            float zP0 = ((b0.x + b1.x) + (b2.x + b3.x)) + nb.x;
            float zP1 = ((b0.y + b1.y) + (b2.y + b3.y)) + nb.y;
            smZ[buf][ty][tx] = make_float4(zG0, zG1, zP0, zP1);
            __syncthreads();

            float4 ys = make_float4(0.f, 0.f, 0.f, 0.f);
            if (ty >= 2 && ty < 30) {
                float4 c0 = smZ[buf][ty-2][tx];
                float4 c1 = smZ[buf][ty-1][tx];
                float4 c2 = smZ[buf][ty  ][tx];
                float4 c3 = smZ[buf][ty+1][tx];
                float4 c4 = smZ[buf][ty+2][tx];
                ys.x = ((c0.x + c1.x) + (c2.x + c3.x)) + c4.x;
                ys.y = ((c0.y + c1.y) + (c2.y + c3.y)) + c4.y;
                ys.z = ((c0.z + c1.z) + (c2.z + c3.z)) + c4.z;
                ys.w = ((c0.w + c1.w) + (c2.w + c3.w)) + c4.w;
            }
            // x-conv: width-16 shuffles, 2 outputs per tensor from 4 shuffles
            float lG0 = __shfl_up_sync(0xffffffffu, ys.x, 1, 16);
            float lG1 = __shfl_up_sync(0xffffffffu, ys.y, 1, 16);
            float rG0 = __shfl_down_sync(0xffffffffu, ys.x, 1, 16);
            float rG1 = __shfl_down_sync(0xffffffffu, ys.y, 1, 16);
            float lP0 = __shfl_up_sync(0xffffffffu, ys.z, 1, 16);
            float lP1 = __shfl_up_sync(0xffffffffu, ys.w, 1, 16);
            float rP0 = __shfl_down_sync(0xffffffffu, ys.z, 1, 16);
            float rP1 = __shfl_down_sync(0xffffffffu, ys.w, 1, 16);

            float csG = ys.x + ys.y;
            float csP = ys.z + ys.w;
            if (v0) {
                float mg = (csG + (lG0 + lG1) + rG0) * 0.008f;   // 1/125
                float mp = (csP + (lP0 + lP1) + rP0) * 0.008f;
                float dg = a2.x - mg;
                float dp = b2.x - mp;
                agg = fmaf(dg, dg, agg);
                app = fmaf(dp, dp, app);
                agp = fmaf(dg, dp, agp);
            }
            if (v1) {
                float mg = (csG + lG1 + (rG0 + rG1)) * 0.008f;
                float mp = (csP + lP1 + (rP0 + rP1)) * 0.008f;
                float dg = a2.y - mg;
                float dp = b2.y - mp;
                agg = fmaf(dg, dg, agg);
                app = fmaf(dp, dp, app);
                agp = fmaf(dg, dp, agp);
            }
            // slide window (no trailing sync: next iter writes other buffer)
            a0 = a1; a1 = a2; a2 = a3; a3 = na;
            b0 = b1; b1 = b2; b2 = b3; b3 = nb;
        }

        agg = warpSum(agg); app = warpSum(app); agp = warpSum(agp);
        if (lane == 0) { red[0][wid] = agg; red[1][wid] = app; red[2][wid] = agp; }
        __syncthreads();
        if (wid == 0) {
            float a = (lane < 16) ? red[0][lane] : 0.f;
            float b = (lane < 16) ? red[1][lane] : 0.f;
            float c = (lane < 16) ? red[2][lane] : 0.f;
            a = warpSum(a); b = warpSum(b); c = warpSum(c);
            if (lane == 0) {
                atomicAdd(&g_acc[accBase + 0], (double)a);
                atomicAdd(&g_acc[accBase + 1], (double)b);
                atomicAdd(&g_acc[accBase + 2], (double)c);
            }
        }
    } else if (bid < NLCC + NREG) {
        // ---------------- reg_field: branch-free stream ----------------
        const int R = FVOL / 4;
        const int stride = NREG * 512;
        float s = 0.f;
        const float4* __restrict__ a4 = (const float4*)F0;
        const float4* __restrict__ b4 = (const float4*)F0g;
#pragma unroll 4
        for (int i = (bid - NLCC) * 512 + lin; i < R; i += stride) {
            float4 a = a4[i], b = b4[i];
            float d0 = a.x - b.x, d1 = a.y - b.y, d2 = a.z - b.z, d3 = a.w - b.w;
            s += (d0 * d0 + d1 * d1) + (d2 * d2 + d3 * d3);
        }
        s = warpSum(s);
        if (lane == 0) red[0][wid] = s;
        __syncthreads();
        if (wid == 0) {
            float v = (lane < 16) ? red[0][lane] : 0.f;
            v = warpSum(v);
            if (lane == 0) atomicAdd(&g_acc[0], (double)v);
        }
    } else {
        // ---------------- tversky ----------------
        const int which = (bid - NLCC - NREG) / NTV;
        const int rb    = (bid - NLCC - NREG) % NTV;
        const float4* __restrict__ g4 = (const float4*)(which ? S1  : S0);
        const float4* __restrict__ p4 = (const float4*)(which ? S1g : S0g);
        const int accBase = 7 + 2 * which;
        const int T = VOL / 4;
        const int stride = NTV * 512;
        float sgp = 0.f, ssm = 0.f;
#pragma unroll 4
        for (int i = rb * 512 + lin; i < T; i += stride) {
            float4 a = g4[i], b = p4[i];
            sgp += (a.x * b.x + a.y * b.y) + (a.z * b.z + a.w * b.w);
            ssm += ((a.x + b.x) + (a.y + b.y)) + ((a.z + b.z) + (a.w + b.w));
        }
        sgp = warpSum(sgp); ssm = warpSum(ssm);
        if (lane == 0) { red[0][wid] = sgp; red[1][wid] = ssm; }
        __syncthreads();
        if (wid == 0) {
            float a = (lane < 16) ? red[0][lane] : 0.f;
            float b = (lane < 16) ? red[1][lane] : 0.f;
            a = warpSum(a); b = warpSum(b);
            if (lane == 0) {
                atomicAdd(&g_acc[accBase + 0], (double)a);
                atomicAdd(&g_acc[accBase + 1], (double)b);
            }
        }
    }

    // -------- last-block finalize ----------------------------------------
    if (lin == 0) {
        __threadfence();
        unsigned int old = atomicAdd(&g_done, 1u);
        if (old == NTOT - 1) {
            double a0 = accRead(0), a1 = accRead(1), a2 = accRead(2), a3 = accRead(3);
            double a4 = accRead(4), a5 = accRead(5), a6 = accRead(6), a7 = accRead(7);
            double a8 = accRead(8), a9 = accRead(9), a10 = accRead(10);

            double reg = sqrt(a0) / (double)FVOL;
            double den0 = a1 * a2; if (den0 < 1e-5) den0 = 1e-5;
            double lcc0 = -((a3 * a3) / den0) / (double)VOL;
            double den1 = a4 * a5; if (den1 < 1e-5) den1 = 1e-5;
            double lcc1 = -((a6 * a6) / den1) / (double)VOL;
            double ds0 = a8;  if (ds0 < 1e-5) ds0 = 1e-5;
            double tv0 = -a7 / ds0;
            double ds1 = a10; if (ds1 < 1e-5) ds1 = 1e-5;
            double tv1 = -a9 / ds1;

            out[0] = (float)(reg + 10.0 * (lcc0 + lcc1) + 10.0 * (tv0 + tv1));

#pragma unroll
            for (int k = 0; k < 12; k++) g_acc[k] = 0.0;
            __threadfence();
            g_done = 0u;
        }
    }
}

extern "C" void kernel_launch(void* const* d_in, const int* in_sizes, int n_in,
                              void* d_out, int out_size) {
    const float* F0  = (const float*)d_in[0];
    const float* F0g = (const float*)d_in[1];
    const float* I0  = (const float*)d_in[2];
    const float* I0R = (const float*)d_in[3];
    const float* I1  = (const float*)d_in[4];
    const float* I1R = (const float*)d_in[5];
    const float* S0  = (const float*)d_in[6];
    const float* S0g = (const float*)d_in[7];
    const float* S1  = (const float*)d_in[8];
    const float* S1g = (const float*)d_in[9];
    float* out = (float*)d_out;

    dim3 blk(16, 32);
    fused_main<<<NTOT, blk>>>(F0, F0g, I0, I0R, I1, I1R, S0, S0g, S1, S1g, out);
}

// round 12
// speedup vs baseline: 1.3547x; 1.3547x over previous
#include <cuda_runtime.h>
#include <math.h>

#define BVOL  (128*128*128)
#define VOL   (2*BVOL)          // 4,194,304
#define PLANE (128*128)
#define FVOL  (2*3*BVOL)        // 12,582,912

#define NLCC 1760               // 5x11 xy-tiles * 8 z-segs * 2 pairs * 2 batches
#define NREG 364
#define NTV  122
#define NTOT (NLCC + NREG + 2*NTV)   // 2368 = 4 waves at 4 CTAs/SM

__device__ double g_acc[12];    // zero-init; finalizer re-zeros each launch
__device__ unsigned int g_done;
// 0 reg | 1 gg0 2 pp0 3 gp0 | 4 gg1 5 pp1 6 gp1 | 7 tvgp0 8 tvsum0 | 9 tvgp1 10 tvsum1

__device__ __forceinline__ float warpSum(float v) {
#pragma unroll
    for (int o = 16; o; o >>= 1) v += __shfl_down_sync(0xffffffffu, v, o);
    return v;
}

__device__ __forceinline__ double accRead(int i) {
    return atomicAdd(&g_acc[i], 0.0);
}

// ---------------------------------------------------------------------------
// LCC inner loop, specialized on guarding.
// GCOL: some threads' columns are out of bounds (use zlimit = -1 for them).
// GZ:   the z-segment touches z=128 (needs per-iter z bound check).
// ---------------------------------------------------------------------------
template<bool GCOL, bool GZ>
__device__ __forceinline__ void lcc_loop(
    const float* __restrict__ gt, const float* __restrict__ pr,
    int cbase, int z0, int zlimit, bool inter,
    float2 (*smZ)[16][32], int tx, int ty,
    float g0, float g1, float g2, float g3,
    float p0, float p1, float p2, float p3,
    float& agg, float& app, float& agp)
{
#pragma unroll 4
    for (int zi = 0; zi < 16; zi++) {
        const int buf = zi & 1;
        const int zl  = z0 + zi + 2;
        float ng, np;
        if (GCOL || GZ) {
            ng = 0.f; np = 0.f;
            if (zl < zlimit) {
                ng = gt[cbase + zl * PLANE];
                np = pr[cbase + zl * PLANE];
            }
        } else {
            ng = gt[cbase + zl * PLANE];
            np = pr[cbase + zl * PLANE];
        }
        smZ[buf][ty][tx] = make_float2(((g0 + g1) + (g2 + g3)) + ng,
                                       ((p0 + p1) + (p2 + p3)) + np);
        __syncthreads();

        float ysG = 0.f, ysP = 0.f;
        if (ty >= 2 && ty < 14) {
            float2 a = smZ[buf][ty-2][tx];
            float2 b = smZ[buf][ty-1][tx];
            float2 c = smZ[buf][ty  ][tx];
            float2 d = smZ[buf][ty+1][tx];
            float2 e = smZ[buf][ty+2][tx];
            ysG = ((a.x + b.x) + (c.x + d.x)) + e.x;
            ysP = ((a.y + b.y) + (c.y + d.y)) + e.y;
        }
        float gGm2 = __shfl_up_sync(0xffffffffu, ysG, 2);
        float gGm1 = __shfl_up_sync(0xffffffffu, ysG, 1);
        float gGp1 = __shfl_down_sync(0xffffffffu, ysG, 1);
        float gGp2 = __shfl_down_sync(0xffffffffu, ysG, 2);
        float gPm2 = __shfl_up_sync(0xffffffffu, ysP, 2);
        float gPm1 = __shfl_up_sync(0xffffffffu, ysP, 1);
        float gPp1 = __shfl_down_sync(0xffffffffu, ysP, 1);
        float gPp2 = __shfl_down_sync(0xffffffffu, ysP, 2);
        if (inter) {
            float mg = (((gGm2 + gGm1) + (ysG + gGp1)) + gGp2) * 0.008f;  // 1/125
            float mp = (((gPm2 + gPm1) + (ysP + gPp1)) + gPp2) * 0.008f;
            float dg = g2 - mg;
            float dp = p2 - mp;
            agg = fmaf(dg, dg, agg);
            app = fmaf(dp, dp, app);
            agp = fmaf(dg, dp, agp);
        }
        // no trailing sync: next iter writes the other buffer.
        g0 = g1; g1 = g2; g2 = g3; g3 = ng;
        p0 = p1; p1 = p2; p2 = p3; p3 = np;
    }
}

__global__ void __launch_bounds__(512, 4)
fused_main(const float* __restrict__ F0,  const float* __restrict__ F0g,
           const float* __restrict__ I0,  const float* __restrict__ I0R,
           const float* __restrict__ I1,  const float* __restrict__ I1R,
           const float* __restrict__ S0,  const float* __restrict__ S0g,
           const float* __restrict__ S1,  const float* __restrict__ S1g,
           float* __restrict__ out) {
    __shared__ float2 smZ[2][16][32];   // (G,P) packed
    __shared__ float red[5][16];

    const int tx  = threadIdx.x;          // warp = x-row
    const int ty  = threadIdx.y;          // 0..15
    const int lin = ty * 32 + tx;
    const int lane = lin & 31, wid = lin >> 5;
    const int bid = blockIdx.x;

    if (bid < NLCC) {
        // ---------------- fully fused LCC ----------------
        int t = bid;
        int pb   = t & 3;  t >>= 2;      // pair*2 + batch
        int zseg = t & 7;  t >>= 3;      // 8 z-segments of 16
        int tyid = t % 11;               // 11 y-tiles of 12
        int txid = t / 11;               // 5 x-tiles of 28
        int pair = pb >> 1, n = pb & 1;
        const float* __restrict__ gt = pair ? I1  : I0;
        const float* __restrict__ pr = pair ? I1R : I0R;
        const int accBase = 1 + 3 * pair;

        const int x0 = txid * 28, y0 = tyid * 12, z0 = zseg * 16;
        const int gx = x0 + tx - 2, gy = y0 + ty - 2;
        const bool colValid = (gx >= 0) && (gx < 128) && (gy >= 0) && (gy < 128);
        const bool inter = (tx >= 2) && (tx < 30) && (ty >= 2) && (ty < 14) &&
                           (gx < 128) && (gy < 128);
        const int cbase = n * BVOL + gy * 128 + gx;
        const int zlimit = colValid ? 128 : -1;     // single compare covers both guards

        // block-uniform classification
        const bool blockInterior = (txid >= 1) && (txid <= 3) && (tyid >= 1) && (tyid <= 9);
        const bool zhi = (zseg == 7);

        // 5-plane sliding window prologue (always guarded; outside hot loop)
        float g0 = 0.f, g1 = 0.f, g2 = 0.f, g3 = 0.f;
        float p0 = 0.f, p1 = 0.f, p2 = 0.f, p3 = 0.f;
        if (colValid) {
            if (z0 >= 2) { g0 = gt[cbase + (z0-2) * PLANE]; p0 = pr[cbase + (z0-2) * PLANE]; }
            if (z0 >= 1) { g1 = gt[cbase + (z0-1) * PLANE]; p1 = pr[cbase + (z0-1) * PLANE]; }
            g2 = gt[cbase + z0 * PLANE];       p2 = pr[cbase + z0 * PLANE];
            g3 = gt[cbase + (z0+1) * PLANE];   p3 = pr[cbase + (z0+1) * PLANE];
        }

        float agg = 0.f, app = 0.f, agp = 0.f;

        if (blockInterior && !zhi) {
            lcc_loop<false, false>(gt, pr, cbase, z0, zlimit, inter, smZ, tx, ty,
                                   g0, g1, g2, g3, p0, p1, p2, p3, agg, app, agp);
        } else if (!zhi) {
            lcc_loop<true, false>(gt, pr, cbase, z0, zlimit, inter, smZ, tx, ty,
                                  g0, g1, g2, g3, p0, p1, p2, p3, agg, app, agp);
        } else {
            lcc_loop<true, true>(gt, pr, cbase, z0, zlimit, inter, smZ, tx, ty,
                                 g0, g1, g2, g3, p0, p1, p2, p3, agg, app, agp);
        }

        agg = warpSum(agg); app = warpSum(app); agp = warpSum(agp);
        if (lane == 0) { red[0][wid] = agg; red[1][wid] = app; red[2][wid] = agp; }
        __syncthreads();
        if (wid == 0) {
            float a = (lane < 16) ? red[0][lane] : 0.f;
            float b = (lane < 16) ? red[1][lane] : 0.f;
            float c = (lane < 16) ? red[2][lane] : 0.f;
            a = warpSum(a); b = warpSum(b); c = warpSum(c);
            if (lane == 0) {
                atomicAdd(&g_acc[accBase + 0], (double)a);
                atomicAdd(&g_acc[accBase + 1], (double)b);
                atomicAdd(&g_acc[accBase + 2], (double)c);
            }
        }
    } else if (bid < NLCC + NREG) {
        // ---------------- reg_field: branch-free stream ----------------
        const int R = FVOL / 4;
        const int stride = NREG * 512;
        float s = 0.f;
        const float4* __restrict__ a4 = (const float4*)F0;
        const float4* __restrict__ b4 = (const float4*)F0g;
#pragma unroll 4
        for (int i = (bid - NLCC) * 512 + lin; i < R; i += stride) {
            float4 a = a4[i], b = b4[i];
            float d0 = a.x - b.x, d1 = a.y - b.y, d2 = a.z - b.z, d3 = a.w - b.w;
            s += (d0 * d0 + d1 * d1) + (d2 * d2 + d3 * d3);
        }
        s = warpSum(s);
        if (lane == 0) red[0][wid] = s;
        __syncthreads();
        if (wid == 0) {
            float v = (lane < 16) ? red[0][lane] : 0.f;
            v = warpSum(v);
            if (lane == 0) atomicAdd(&g_acc[0], (double)v);
        }
    } else {
        // ---------------- tversky ----------------
        const int which = (bid - NLCC - NREG) / NTV;
        const int rb    = (bid - NLCC - NREG) % NTV;
        const float4* __restrict__ g4 = (const float4*)(which ? S1  : S0);
        const float4* __restrict__ p4 = (const float4*)(which ? S1g : S0g);
        const int accBase = 7 + 2 * which;
        const int T = VOL / 4;
        const int stride = NTV * 512;
        float sgp = 0.f, ssm = 0.f;
#pragma unroll 4
        for (int i = rb * 512 + lin; i < T; i += stride) {
            float4 a = g4[i], b = p4[i];
            sgp += (a.x * b.x + a.y * b.y) + (a.z * b.z + a.w * b.w);
            ssm += ((a.x + b.x) + (a.y + b.y)) + ((a.z + b.z) + (a.w + b.w));
        }
        sgp = warpSum(sgp); ssm = warpSum(ssm);
        if (lane == 0) { red[0][wid] = sgp; red[1][wid] = ssm; }
        __syncthreads();
        if (wid == 0) {
            float a = (lane < 16) ? red[0][lane] : 0.f;
            float b = (lane < 16) ? red[1][lane] : 0.f;
            a = warpSum(a); b = warpSum(b);
            if (lane == 0) {
                atomicAdd(&g_acc[accBase + 0], (double)a);
                atomicAdd(&g_acc[accBase + 1], (double)b);
            }
        }
    }

    // -------- last-block finalize ----------------------------------------
    if (lin == 0) {
        __threadfence();
        unsigned int old = atomicAdd(&g_done, 1u);
        if (old == NTOT - 1) {
            double a0 = accRead(0), a1 = accRead(1), a2 = accRead(2), a3 = accRead(3);
            double a4 = accRead(4), a5 = accRead(5), a6 = accRead(6), a7 = accRead(7);
            double a8 = accRead(8), a9 = accRead(9), a10 = accRead(10);

            double reg = sqrt(a0) / (double)FVOL;
            double den0 = a1 * a2; if (den0 < 1e-5) den0 = 1e-5;
            double lcc0 = -((a3 * a3) / den0) / (double)VOL;
            double den1 = a4 * a5; if (den1 < 1e-5) den1 = 1e-5;
            double lcc1 = -((a6 * a6) / den1) / (double)VOL;
            double ds0 = a8;  if (ds0 < 1e-5) ds0 = 1e-5;
            double tv0 = -a7 / ds0;
            double ds1 = a10; if (ds1 < 1e-5) ds1 = 1e-5;
            double tv1 = -a9 / ds1;

            out[0] = (float)(reg + 10.0 * (lcc0 + lcc1) + 10.0 * (tv0 + tv1));

#pragma unroll
            for (int k = 0; k < 12; k++) g_acc[k] = 0.0;
            __threadfence();
            g_done = 0u;
        }
    }
}

extern "C" void kernel_launch(void* const* d_in, const int* in_sizes, int n_in,
                              void* d_out, int out_size) {
    const float* F0  = (const float*)d_in[0];
    const float* F0g = (const float*)d_in[1];
    const float* I0  = (const float*)d_in[2];
    const float* I0R = (const float*)d_in[3];
    const float* I1  = (const float*)d_in[4];
    const float* I1R = (const float*)d_in[5];
    const float* S0  = (const float*)d_in[6];
    const float* S0g = (const float*)d_in[7];
    const float* S1  = (const float*)d_in[8];
    const float* S1g = (const float*)d_in[9];
    float* out = (float*)d_out;

    dim3 blk(32, 16);
    fused_main<<<NTOT, blk>>>(F0, F0g, I0, I0R, I1, I1R, S0, S0g, S1, S1g, out);
}